// round 7
// baseline (speedup 1.0000x reference)
#include <cuda_runtime.h>
#include <math.h>

__device__ float g_h1[(size_t)512 * 32 * 144];
__device__ float g_h4[(size_t)512 * 64 * 144];
__device__ float g_xz[(size_t)512 * 64 * 576];

__device__ __forceinline__ float d4(float4 a, float4 b) {
    return a.x * b.x + a.y * b.y + a.z * b.z + a.w * b.w;
}

// ============ kernel 1: conv1(200->32,3x3,pad1)+BN+ReLU ============
// 1 image per CTA, 144 threads, 6 CTAs/SM. thread = 2row x 4col x 4oc.
__global__ void __launch_bounds__(144, 6) k_front(
    const float* __restrict__ x, const float* __restrict__ w1,
    const float* __restrict__ b1, const float* __restrict__ g1,
    const float* __restrict__ be1, const float* __restrict__ m1,
    const float* __restrict__ v1)
{
    __shared__ float xs[8 * 196];        // 8 ic x 14x14 padded
    __shared__ float ws[8 * 288];        // [ic][tap][32oc]
    int tid = threadIdx.x;
    int pg = tid % 18, ocg = tid / 18;   // 18 pos-tiles, 8 oc-groups(4oc)
    int ry = (pg / 3) * 2, cx = (pg % 3) * 4;
    size_t bi = blockIdx.x;
    float acc[2][4][4] = {};
    const float* xb = x + bi * 28800;
    for (int i = tid; i < 1568; i += 144) xs[i] = 0.f;

    for (int c0 = 0; c0 < 200; c0 += 8) {
        __syncthreads();
        for (int i = tid; i < 1152; i += 144) {
            int ic = i / 144, pos = i - ic * 144;
            int y = pos / 12, xx = pos - y * 12;
            xs[ic * 196 + (y + 1) * 14 + xx + 1] = xb[(c0 + ic) * 144 + pos];
        }
        for (int i = tid; i < 2304; i += 144) {
            int ic = i / 288, rr = i - ic * 288;
            ws[i] = w1[(rr & 31) * 1800 + (c0 + ic) * 9 + (rr >> 5)];
        }
        __syncthreads();
#pragma unroll 1
        for (int ic = 0; ic < 8; ic++) {
            float xv[4][6];
            const float* xp = &xs[ic * 196 + ry * 14 + cx];
#pragma unroll
            for (int rr = 0; rr < 4; rr++)
#pragma unroll
                for (int cc = 0; cc < 6; cc++) xv[rr][cc] = xp[rr * 14 + cc];
#pragma unroll
            for (int k = 0; k < 9; k++) {
                float4 wv = *(const float4*)&ws[ic * 288 + k * 32 + ocg * 4];
                int kr = k / 3, kc = k % 3;
#pragma unroll
                for (int orow = 0; orow < 2; orow++)
#pragma unroll
                    for (int q = 0; q < 4; q++) {
                        float xvv = xv[orow + kr][kc + q];
                        acc[orow][0][q] += wv.x * xvv;
                        acc[orow][1][q] += wv.y * xvv;
                        acc[orow][2][q] += wv.z * xvv;
                        acc[orow][3][q] += wv.w * xvv;
                    }
            }
        }
    }
#pragma unroll
    for (int o = 0; o < 4; o++) {
        int oc = ocg * 4 + o;
        float inv = g1[oc] * rsqrtf(v1[oc] + 1e-5f);
        float sh = (b1[oc] - m1[oc]) * inv + be1[oc];
#pragma unroll
        for (int orow = 0; orow < 2; orow++) {
            float4 v;
            v.x = fmaxf(acc[orow][o][0] * inv + sh, 0.f);
            v.y = fmaxf(acc[orow][o][1] * inv + sh, 0.f);
            v.z = fmaxf(acc[orow][o][2] * inv + sh, 0.f);
            v.w = fmaxf(acc[orow][o][3] * inv + sh, 0.f);
            *(float4*)&g_h1[bi * 4608 + oc * 144 + (ry + orow) * 12 + cx] = v;
        }
    }
}

// ============ kernel 2: conv2+BN+ReLU -> we -> wc2 -> in_w ============
// arena 28160 fl: stage[0,..), h3[9216,18688) stride148, h2/h4[18688,28160) stride148
__global__ void __launch_bounds__(288, 2) k_mid(
    const float* __restrict__ w2, const float* __restrict__ b2,
    const float* __restrict__ g2, const float* __restrict__ be2,
    const float* __restrict__ m2, const float* __restrict__ v2,
    const float* __restrict__ wc2, const float* __restrict__ bc2,
    const float* __restrict__ we, const float* __restrict__ bee,
    const float* __restrict__ in_w)
{
    extern __shared__ float sm[];
    float* ws2 = sm;                 // phase A [ic][tap][64oc] 4608
    float* img = sm + 4608;          // phase A padded 32x196 = 6272
    float* stage = sm;
    float* h3 = sm + 9216;
    float* h2 = sm + 18688;
    float* h4 = sm + 18688;
    int bi = blockIdx.x, tid = threadIdx.x;

    // ---- phase A: conv2(32->64)+BN+ReLU, all 288 threads: 18 pos x 16 ocg x 4oc ----
    for (int i = tid; i < 6272; i += 288) img[i] = 0.f;
    __syncthreads();
    for (int i = tid; i < 4608; i += 288) {
        int ic = i / 144, pos = i - ic * 144;
        int y = pos / 12, xx = pos - y * 12;
        img[ic * 196 + (y + 1) * 14 + xx + 1] = g_h1[(size_t)bi * 4608 + i];
    }
    {
        int pg = tid % 18, ocg = tid / 18;       // ocg 0..15
        int ry = (pg / 3) * 2, cx = (pg % 3) * 4;
        float acc[2][4][4] = {};
        for (int c0 = 0; c0 < 32; c0 += 8) {
            __syncthreads();
            for (int i = tid; i < 4608; i += 288) {
                int ic = i / 576, rr = i - ic * 576;
                ws2[i] = w2[(rr & 63) * 288 + (c0 + ic) * 9 + (rr >> 6)];
            }
            __syncthreads();
#pragma unroll 1
            for (int ic = 0; ic < 8; ic++) {
                float xv[4][6];
                const float* xp = &img[(c0 + ic) * 196 + ry * 14 + cx];
#pragma unroll
                for (int rr = 0; rr < 4; rr++)
#pragma unroll
                    for (int cc = 0; cc < 6; cc++) xv[rr][cc] = xp[rr * 14 + cc];
#pragma unroll
                for (int k = 0; k < 9; k++) {
                    float4 wv = *(const float4*)&ws2[ic * 576 + k * 64 + ocg * 4];
                    int kr = k / 3, kc = k % 3;
#pragma unroll
                    for (int orow = 0; orow < 2; orow++)
#pragma unroll
                        for (int q = 0; q < 4; q++) {
                            float xvv = xv[orow + kr][kc + q];
                            acc[orow][0][q] += wv.x * xvv;
                            acc[orow][1][q] += wv.y * xvv;
                            acc[orow][2][q] += wv.z * xvv;
                            acc[orow][3][q] += wv.w * xvv;
                        }
                }
            }
        }
#pragma unroll
        for (int o = 0; o < 4; o++) {
            int oc = ocg * 4 + o;
            float inv = g2[oc] * rsqrtf(v2[oc] + 1e-5f);
            float sh = (b2[oc] - m2[oc]) * inv + be2[oc];
#pragma unroll
            for (int orow = 0; orow < 2; orow++)
#pragma unroll
                for (int q = 0; q < 4; q++)
                    h2[oc * 148 + (ry + orow) * 12 + cx + q] =
                        fmaxf(acc[orow][o][q] * inv + sh, 0.f);
        }
    }

    // ---- phase B: h3 = h2 @ we^T + bee (broadcast, 36-o chunks x 8 tc) ----
    {
        int oslot = tid % 36, tc = tid / 36;     // tc 0..7
        const float4* h24 = (const float4*)h2;
        for (int o0 = 0; o0 < 144; o0 += 36) {
            __syncthreads();
            for (int i = tid; i < 36 * 144; i += 288) {
                int o = i / 144, k = i - o * 144;
                stage[o * 148 + k] = we[(o0 + o) * 144 + k];
            }
            __syncthreads();
            float acc[8] = {};
            const float4* w4 = (const float4*)&stage[oslot * 148];
            int tb = tc * 8;
            for (int k4 = 0; k4 < 36; k4++) {
                float4 wv = w4[k4];
#pragma unroll
                for (int t = 0; t < 8; t++)
                    acc[t] += d4(h24[(tb + t) * 37 + k4], wv);
            }
            float bb = bee[o0 + oslot];
#pragma unroll
            for (int t = 0; t < 8; t++)
                h3[(tb + t) * 148 + o0 + oslot] = acc[t] + bb;
        }
    }

    // ---- phase C: h4 = wc2-mix(h3)+bc2 (token mix, 4x4 tiles) ----
    __syncthreads();
    for (int i = tid; i < 4096; i += 288) {
        int li = i >> 6, lo = i & 63;
        stage[i] = wc2[lo * 64 + li];
    }
    __syncthreads();
    for (int tt = tid; tt < 576; tt += 288) {
        int pt = tt % 36, lt = tt / 36;
        int p0 = pt * 4, lo0 = lt * 4;
        float a[4][4] = {};
        for (int li = 0; li < 64; li++) {
            float4 w4 = *(const float4*)&stage[li * 64 + lo0];
            float4 x4 = *(const float4*)&h3[li * 148 + p0];
            a[0][0] += w4.x * x4.x; a[0][1] += w4.x * x4.y; a[0][2] += w4.x * x4.z; a[0][3] += w4.x * x4.w;
            a[1][0] += w4.y * x4.x; a[1][1] += w4.y * x4.y; a[1][2] += w4.y * x4.z; a[1][3] += w4.y * x4.w;
            a[2][0] += w4.z * x4.x; a[2][1] += w4.z * x4.y; a[2][2] += w4.z * x4.z; a[2][3] += w4.z * x4.w;
            a[3][0] += w4.w * x4.x; a[3][1] += w4.w * x4.y; a[3][2] += w4.w * x4.z; a[3][3] += w4.w * x4.w;
        }
#pragma unroll
        for (int r = 0; r < 4; r++) {
            float bb = bc2[lo0 + r];
            float4 st = {a[r][0] + bb, a[r][1] + bb, a[r][2] + bb, a[r][3] + bb};
            *(float4*)&h4[(lo0 + r) * 148 + p0] = st;
            *(float4*)&g_h4[(size_t)bi * 9216 + (lo0 + r) * 144 + p0] = st;
        }
    }

    // ---- phase D: xz = h4 @ in_w^T -> g_xz (broadcast, 72-o chunks x 4 tc) ----
    {
        int oslot = tid % 72, tc = tid / 72;     // tc 0..3
        const float4* h44 = (const float4*)h4;
        for (int o0 = 0; o0 < 576; o0 += 72) {
            __syncthreads();
            for (int i = tid; i < 72 * 144; i += 288) {
                int o = i / 144, k = i - o * 144;
                stage[o * 148 + k] = in_w[(o0 + o) * 144 + k];
            }
            __syncthreads();
            float acc[16] = {};
            const float4* w4 = (const float4*)&stage[oslot * 148];
            int tb = tc * 16;
            for (int k4 = 0; k4 < 36; k4++) {
                float4 wv = w4[k4];
#pragma unroll
                for (int t = 0; t < 16; t++)
                    acc[t] += d4(h44[(tb + t) * 37 + k4], wv);
            }
#pragma unroll
            for (int t = 0; t < 16; t++)
                g_xz[(size_t)bi * 36864 + (tb + t) * 576 + o0 + oslot] = acc[t];
        }
    }
}

// ============ kernel 3: mamba + residual + wc3 + BN + ReLU ============
__global__ void __launch_bounds__(288, 2) k_mamba(
    const float* __restrict__ convd_w, const float* __restrict__ convd_b,
    const float* __restrict__ xproj_w, const float* __restrict__ dtproj_w,
    const float* __restrict__ dtproj_b, const float* __restrict__ A_log,
    const float* __restrict__ Dp, const float* __restrict__ out_w,
    const float* __restrict__ wc3, const float* __restrict__ bc3,
    const float* __restrict__ g3, const float* __restrict__ be3,
    const float* __restrict__ m3, const float* __restrict__ v3,
    float* __restrict__ out)
{
    extern __shared__ float sm[];
    float* uY = sm;                  // 18432
    float* dbl = sm + 18432;         // 3072 (overlaid by rS later)
    float* rS = sm + 18432;          // 9216
    int bi = blockIdx.x, c = threadIdx.x;
    const float* xzb = g_xz + (size_t)bi * 36864;

    {
        const float4* src = (const float4*)xzb;
        float4* dst = (float4*)uY;
        for (int i = c; i < 4608; i += 288) {
            int t = i / 72, ch4 = i - t * 72;
            dst[t * 72 + ch4] = src[t * 144 + ch4];
        }
    }
    __syncthreads();

    // depthwise causal conv (DC=4) + SiLU, in place, thread=channel
    {
        float cw0 = convd_w[c * 4], cw1 = convd_w[c * 4 + 1],
              cw2 = convd_w[c * 4 + 2], cw3 = convd_w[c * 4 + 3];
        float cb = convd_b[c];
        float p0 = 0.f, p1 = 0.f, p2 = 0.f;
        for (int t = 0; t < 64; t++) {
            float xt = uY[t * 288 + c];
            float s = cw0 * p0 + cw1 * p1 + cw2 * p2 + cw3 * xt + cb;
            s = s / (1.f + __expf(-s));
            uY[t * 288 + c] = s;
            p0 = p1; p1 = p2; p2 = xt;
        }
    }
    __syncthreads();

    // xproj (broadcast): thread = (tc 0..3, j 0..40), 16 t each
    if (c < 164) {
        int j = c % 41, tc = c / 41;
        float acc[16] = {};
        const float4* xw4 = (const float4*)&xproj_w[j * 288];
        const float4* uY4 = (const float4*)uY;
        int tb = tc * 16;
        float4 wv = __ldg(&xw4[0]);
        for (int k4 = 0; k4 < 72; k4++) {
            float4 wn = (k4 < 71) ? __ldg(&xw4[k4 + 1]) : wv;
#pragma unroll
            for (int t = 0; t < 16; t++)
                acc[t] += d4(uY4[(tb + t) * 72 + k4], wv);
            wv = wn;
        }
#pragma unroll
        for (int t = 0; t < 16; t++) dbl[(tb + t) * 48 + j] = acc[t];
    }
    __syncthreads();

    // selective scan + gate (thread=channel, 16 states in regs)
    {
        float dtw[9], A[16], h[16];
#pragma unroll
        for (int r = 0; r < 9; r++) dtw[r] = dtproj_w[c * 9 + r];
        float dtb = dtproj_b[c];
#pragma unroll
        for (int n = 0; n < 16; n++) { A[n] = -__expf(A_log[c * 16 + n]); h[n] = 0.f; }
        float dpc = Dp[c];
        for (int t = 0; t < 64; t++) {
            float zv = xzb[t * 576 + 288 + c];
            float dt = dtb;
#pragma unroll
            for (int r = 0; r < 9; r++) dt += dbl[t * 48 + r] * dtw[r];
            float delta = fmaxf(dt, 0.f) + log1pf(__expf(-fabsf(dt)));
            float u = uY[t * 288 + c];
            float dlu = delta * u;
            float y = 0.f;
#pragma unroll
            for (int n = 0; n < 16; n++) {
                float e = __expf(delta * A[n]);
                h[n] = h[n] * e + dlu * dbl[t * 48 + 9 + n];
                y += h[n] * dbl[t * 48 + 25 + n];
            }
            float sz = zv / (1.f + __expf(-zv));
            uY[t * 288 + c] = (y + u * dpc) * sz;
        }
    }
    __syncthreads();

    // out-proj (broadcast) + residual -> rS: thread = (tc 0..1, o 0..143), 32 t
    {
        int o = c % 144, tc = c / 144;
        float acc[32] = {};
        const float4* ow4 = (const float4*)&out_w[o * 288];
        const float4* uY4 = (const float4*)uY;
        int tb = tc * 32;
        float4 wv = __ldg(&ow4[0]);
        for (int k4 = 0; k4 < 72; k4++) {
            float4 wn = (k4 < 71) ? __ldg(&ow4[k4 + 1]) : wv;
#pragma unroll
            for (int t = 0; t < 32; t++)
                acc[t] += d4(uY4[(tb + t) * 72 + k4], wv);
            wv = wn;
        }
        const float* resb = g_h4 + (size_t)bi * 9216;
#pragma unroll
        for (int t = 0; t < 32; t++) {
            int tt = tb + t;
            rS[tt * 144 + o] = acc[t] + __ldg(&resb[tt * 144 + o]);
        }
    }
    __syncthreads();

    // wc3 (64->32 token mix) + BN + ReLU -> out, 4x4 tiles
    for (int i = c; i < 2048; i += 288) {
        int li = i >> 5, oc = i & 31;
        uY[i] = wc3[oc * 64 + li];
    }
    __syncthreads();
    {
        int pt = c % 36, ot = c / 36;
        int p0 = pt * 4, oc0 = ot * 4;
        float a[4][4] = {};
        for (int li = 0; li < 64; li++) {
            float4 w4 = *(const float4*)&uY[li * 32 + oc0];
            float4 x4 = *(const float4*)&rS[li * 144 + p0];
            a[0][0] += w4.x * x4.x; a[0][1] += w4.x * x4.y; a[0][2] += w4.x * x4.z; a[0][3] += w4.x * x4.w;
            a[1][0] += w4.y * x4.x; a[1][1] += w4.y * x4.y; a[1][2] += w4.y * x4.z; a[1][3] += w4.y * x4.w;
            a[2][0] += w4.z * x4.x; a[2][1] += w4.z * x4.y; a[2][2] += w4.z * x4.z; a[2][3] += w4.z * x4.w;
            a[3][0] += w4.w * x4.x; a[3][1] += w4.w * x4.y; a[3][2] += w4.w * x4.z; a[3][3] += w4.w * x4.w;
        }
#pragma unroll
        for (int r = 0; r < 4; r++) {
            int oc = oc0 + r;
            float inv = g3[oc] * rsqrtf(v3[oc] + 1e-5f);
            float sh = (bc3[oc] - m3[oc]) * inv + be3[oc];
            float4 st;
            st.x = fmaxf(a[r][0] * inv + sh, 0.f);
            st.y = fmaxf(a[r][1] * inv + sh, 0.f);
            st.z = fmaxf(a[r][2] * inv + sh, 0.f);
            st.w = fmaxf(a[r][3] * inv + sh, 0.f);
            *(float4*)&out[(size_t)bi * 4608 + oc * 144 + p0] = st;
        }
    }
}

extern "C" void kernel_launch(void* const* d_in, const int* in_sizes, int n_in,
                              void* d_out, int out_size)
{
    const float* x       = (const float*)d_in[0];
    const float* w1      = (const float*)d_in[1];
    const float* b1      = (const float*)d_in[2];
    const float* g1      = (const float*)d_in[3];
    const float* be1     = (const float*)d_in[4];
    const float* m1      = (const float*)d_in[5];
    const float* v1      = (const float*)d_in[6];
    const float* w2      = (const float*)d_in[7];
    const float* b2      = (const float*)d_in[8];
    const float* g2      = (const float*)d_in[9];
    const float* be2     = (const float*)d_in[10];
    const float* m2      = (const float*)d_in[11];
    const float* v2      = (const float*)d_in[12];
    const float* wc2     = (const float*)d_in[13];
    const float* bc2     = (const float*)d_in[14];
    const float* we      = (const float*)d_in[15];
    const float* bee     = (const float*)d_in[16];
    const float* in_w    = (const float*)d_in[17];
    const float* convd_w = (const float*)d_in[18];
    const float* convd_b = (const float*)d_in[19];
    const float* xproj_w = (const float*)d_in[20];
    const float* dtproj_w= (const float*)d_in[21];
    const float* dtproj_b= (const float*)d_in[22];
    const float* A_log   = (const float*)d_in[23];
    const float* Dp      = (const float*)d_in[24];
    const float* out_w   = (const float*)d_in[25];
    const float* wc3     = (const float*)d_in[26];
    const float* bc3     = (const float*)d_in[27];
    const float* g3      = (const float*)d_in[28];
    const float* be3     = (const float*)d_in[29];
    const float* m3      = (const float*)d_in[30];
    const float* v3      = (const float*)d_in[31];

    int B = in_sizes[0] / 28800;

    cudaFuncSetAttribute(k_mid, cudaFuncAttributeMaxDynamicSharedMemorySize, 112640);
    cudaFuncSetAttribute(k_mamba, cudaFuncAttributeMaxDynamicSharedMemorySize, 110592);

    k_front<<<B, 144>>>(x, w1, b1, g1, be1, m1, v1);
    k_mid<<<B, 288, 112640>>>(w2, b2, g2, be2, m2, v2, wc2, bc2, we, bee, in_w);
    k_mamba<<<B, 288, 110592>>>(convd_w, convd_b, xproj_w, dtproj_w, dtproj_b,
                                A_log, Dp, out_w, wc3, bc3, g3, be3, m3, v3,
                                (float*)d_out);
}